// round 14
// baseline (speedup 1.0000x reference)
#include <cuda_runtime.h>
#include <cuda_bf16.h>
#include <cstdint>
#include <math.h>

// ===========================================================================
// MoE layer via mma.sync m16n8k16 bf16 (compute_103-safe). bf16-split 3-MMA
// (hi*hi + lo*hi + hi*lo), fp32 accum -> ~1e-5 rel err.
// R14: fast 64x64 transpose (float4 both ways); rconst folded into router
// (R12-validated); convert_x + tile-table build folded into prep kernel.
// Gate+up GEMM sits at visible launch 3 = ncu capture slot (global 5).
// GEMM core = R13/R8-best, unchanged.
// ===========================================================================

#define DIMD   1024
#define NTOK   4096
#define NEXP   8
#define CAP    8192
#define SLOTS  (NTOK * 2)
#define TOT    (SLOTS + NTOK)
#define MAXRT  72                  // max routed M-tiles
#define NTILEY (MAXRT + 32)        // + 32 shared M-tiles

// ---------------- static scratch ----------------
__device__ float g_gbuf[(size_t)TOT * 1024];
__device__ float g_ubuf[(size_t)TOT * 1024];
__device__ float g_ybuf[(size_t)TOT * 1024];
__device__ __nv_bfloat16 g_Xhi[(size_t)NTOK * 1024];
__device__ __nv_bfloat16 g_Xlo[(size_t)NTOK * 1024];
__device__ __nv_bfloat16 g_Hhi[(size_t)TOT * 1024];
__device__ __nv_bfloat16 g_Hlo[(size_t)TOT * 1024];
// transposed ([out][in] = [n][k]) split weights
__device__ __nv_bfloat16 g_WgThi[(size_t)NEXP << 20];
__device__ __nv_bfloat16 g_WgTlo[(size_t)NEXP << 20];
__device__ __nv_bfloat16 g_WuThi[(size_t)NEXP << 20];
__device__ __nv_bfloat16 g_WuTlo[(size_t)NEXP << 20];
__device__ __nv_bfloat16 g_WdThi[(size_t)NEXP << 20];
__device__ __nv_bfloat16 g_WdTlo[(size_t)NEXP << 20];
__device__ __nv_bfloat16 g_sgThi[1 << 20];
__device__ __nv_bfloat16 g_sgTlo[1 << 20];
__device__ __nv_bfloat16 g_suThi[1 << 20];
__device__ __nv_bfloat16 g_suTlo[1 << 20];
__device__ __nv_bfloat16 g_sdThi[1 << 20];
__device__ __nv_bfloat16 g_sdTlo[1 << 20];
__device__ int   g_list[NEXP * CAP];
__device__ int   g_count[NEXP];
__device__ int   g_expert_of[SLOTS];
__device__ float g_wslot[SLOTS];
__device__ int   g_tileE[MAXRT];
__device__ int   g_tileM[MAXRT];
__device__ int   g_ntile_rt;

// ---------------- helpers ----------------
__device__ __forceinline__ uint32_t smem_u32(const void* p) {
    uint32_t a;
    asm("{ .reg .u64 t; cvta.to.shared.u64 t, %1; cvt.u32.u64 %0, t; }"
        : "=r"(a) : "l"(p));
    return a;
}
__device__ __forceinline__ void cp16(uint32_t dst, const void* src) {
    asm volatile("cp.async.cg.shared.global [%0], [%1], 16;" :: "r"(dst), "l"(src));
}
__device__ __forceinline__ void cp_commit() {
    asm volatile("cp.async.commit_group;" ::: "memory");
}
#define CP_WAIT(n) asm volatile("cp.async.wait_group %0;" :: "n"(n) : "memory")

__device__ __forceinline__ void ldsm4(uint32_t* r, uint32_t addr) {
    asm volatile("ldmatrix.sync.aligned.m8n8.x4.shared.b16 {%0,%1,%2,%3}, [%4];"
        : "=r"(r[0]), "=r"(r[1]), "=r"(r[2]), "=r"(r[3]) : "r"(addr));
}
__device__ __forceinline__ void mma16816(float* c, const uint32_t* a,
                                         uint32_t b0, uint32_t b1) {
    asm volatile(
        "mma.sync.aligned.m16n8k16.row.col.f32.bf16.bf16.f32 "
        "{%0,%1,%2,%3}, {%4,%5,%6,%7}, {%8,%9}, {%0,%1,%2,%3};"
        : "+f"(c[0]), "+f"(c[1]), "+f"(c[2]), "+f"(c[3])
        : "r"(a[0]), "r"(a[1]), "r"(a[2]), "r"(a[3]), "r"(b0), "r"(b1));
}

// ---------------------------------------------------------------------------
// router: one warp per token; full concat(x, loop_emb) @ Wr per warp
// (R12-validated). Stable top-2.
// ---------------------------------------------------------------------------
__global__ void router_kernel(const float* __restrict__ x,
                              const float* __restrict__ Wr,
                              const float* __restrict__ loop_table,
                              const int* __restrict__ loop_idx) {
    int warp = threadIdx.x >> 5, lane = threadIdx.x & 31;
    int n = blockIdx.x * 8 + warp;
    if (n >= NTOK) return;
    const float* xr = x + (size_t)n * DIMD;
    const float* le = loop_table + (size_t)loop_idx[0] * DIMD;
    float acc[NEXP];
#pragma unroll
    for (int e = 0; e < NEXP; e++) acc[e] = 0.f;
    for (int d = lane; d < DIMD; d += 32) {
        float xv = xr[d];
        float lv = le[d];
        const float* wr0 = Wr + (size_t)d * NEXP;
        const float* wr1 = Wr + (size_t)(DIMD + d) * NEXP;
#pragma unroll
        for (int e = 0; e < NEXP; e++) acc[e] += xv * wr0[e] + lv * wr1[e];
    }
#pragma unroll
    for (int e = 0; e < NEXP; e++)
#pragma unroll
        for (int off = 16; off > 0; off >>= 1)
            acc[e] += __shfl_down_sync(0xffffffffu, acc[e], off);
    if (lane == 0) {
        float p[NEXP];
#pragma unroll
        for (int e = 0; e < NEXP; e++)
            p[e] = 1.f / (1.f + expf(-acc[e]));
        float b1 = -1.f; int i1 = 0;
#pragma unroll
        for (int e = 0; e < NEXP; e++) if (p[e] > b1) { b1 = p[e]; i1 = e; }
        float b2 = -1.f; int i2 = 0;
#pragma unroll
        for (int e = 0; e < NEXP; e++)
            if (e != i1 && p[e] > b2) { b2 = p[e]; i2 = e; }
        g_expert_of[2 * n]     = i1;  g_wslot[2 * n]     = b1;
        g_expert_of[2 * n + 1] = i2;  g_wslot[2 * n + 1] = b2;
    }
}

// ---------------------------------------------------------------------------
// dispatch: ordered per-expert slot lists
// ---------------------------------------------------------------------------
__global__ void dispatch_kernel() {
    int e = blockIdx.x;
    __shared__ int warp_tot[8];
    __shared__ int warp_off[8];
    __shared__ int s_base;
    if (threadIdx.x == 0) s_base = 0;
    __syncthreads();
    int lane = threadIdx.x & 31, w = threadIdx.x >> 5;
    for (int s0 = 0; s0 < SLOTS; s0 += 256) {
        int s = s0 + threadIdx.x;
        bool f = (g_expert_of[s] == e);
        unsigned bal = __ballot_sync(0xffffffffu, f);
        if (lane == 0) warp_tot[w] = __popc(bal);
        __syncthreads();
        if (threadIdx.x == 0) {
            int a = s_base;
            for (int i = 0; i < 8; i++) { warp_off[i] = a; a += warp_tot[i]; }
            s_base = a;
        }
        __syncthreads();
        if (f) {
            int pos = warp_off[w] + __popc(bal & ((1u << lane) - 1u));
            g_list[e * CAP + pos] = s;
        }
        __syncthreads();
    }
    if (threadIdx.x == 0) g_count[e] = s_base;
}

// ---------------------------------------------------------------------------
// prep: z 0-26 = 64x64 weight transpose+split; z 27-30 = x split;
// tile-table build appended to z==30 block (15,15) thread 0.
// grid (16, 16, 31), 256 threads.
// ---------------------------------------------------------------------------
struct TPArgs {
    const float* s[6];
    __nv_bfloat16* h[6];
    __nv_bfloat16* l[6];
};
__global__ void prep_all_kernel(TPArgs tp, const float* __restrict__ x) {
    __shared__ float tile[64][65];
    int z = blockIdx.z;
    int tid = threadIdx.x;

    if (z >= 27) {
        // ---- x -> split bf16 hi/lo (coalesced) ----
        int blin = (z - 27) * 256 + blockIdx.y * 16 + blockIdx.x;  // 0..1023
        __nv_bfloat162* HI = (__nv_bfloat162*)g_Xhi;
        __nv_bfloat162* LO = (__nv_bfloat162*)g_Xlo;
#pragma unroll
        for (int j = 0; j < 4; j++) {
            size_t i = (size_t)blin * 1024 + j * 256 + tid;   // float4 idx
            float4 v = ((const float4*)x)[i];
            __nv_bfloat16 h0 = __float2bfloat16(v.x), h1 = __float2bfloat16(v.y);
            __nv_bfloat16 h2 = __float2bfloat16(v.z), h3 = __float2bfloat16(v.w);
            HI[2 * i]     = __nv_bfloat162(h0, h1);
            HI[2 * i + 1] = __nv_bfloat162(h2, h3);
            LO[2 * i]     = __nv_bfloat162(__float2bfloat16(v.x - __bfloat162float(h0)),
                                           __float2bfloat16(v.y - __bfloat162float(h1)));
            LO[2 * i + 1] = __nv_bfloat162(__float2bfloat16(v.z - __bfloat162float(h2)),
                                           __float2bfloat16(v.w - __bfloat162float(h3)));
        }
        // ---- tile-table build (once) ----
        if (z == 30 && blockIdx.x == 15 && blockIdx.y == 15 && tid == 0) {
            int a = 0;
            for (int e = 0; e < NEXP; e++) {
                int nt = (g_count[e] + 127) >> 7;
                for (int t = 0; t < nt; t++) {
                    g_tileE[a + t] = e;
                    g_tileM[a + t] = t * 128;
                }
                a += nt;
            }
            g_ntile_rt = a;
        }
        return;
    }

    // ---- 64x64 transpose + split ----
    int g, m;
    if (z < 24) { g = z >> 3; m = z & 7; } else { g = 3 + (z - 24); m = 0; }
    size_t mbase = (size_t)m << 20;
    const float* S = tp.s[g] + mbase;
    __nv_bfloat16* dhi = tp.h[g] + mbase;
    __nv_bfloat16* dlo = tp.l[g] + mbase;
    int k0 = blockIdx.y * 64, n0 = blockIdx.x * 64;

    // load: thread -> rows (tid>>4)+16i, float4 cols (tid&15)*4
    int lr = tid >> 4, lc = (tid & 15) * 4;
#pragma unroll
    for (int i = 0; i < 4; i++) {
        int r = lr + 16 * i;
        float4 v = *(const float4*)(S + (size_t)(k0 + r) * 1024 + n0 + lc);
        tile[r][lc + 0] = v.x;
        tile[r][lc + 1] = v.y;
        tile[r][lc + 2] = v.z;
        tile[r][lc + 3] = v.w;
    }
    __syncthreads();

    // store: two passes of 32 out-rows; thread -> row (tid>>3)+32p, 8 k's
#pragma unroll
    for (int p = 0; p < 2; p++) {
        int nl = (tid >> 3) + 32 * p;
        int kb = (tid & 7) * 8;
        size_t obase = (size_t)(n0 + nl) * 1024 + k0 + kb;
#pragma unroll
        for (int q = 0; q < 2; q++) {
            float v0 = tile[kb + 4 * q + 0][nl];
            float v1 = tile[kb + 4 * q + 1][nl];
            float v2 = tile[kb + 4 * q + 2][nl];
            float v3 = tile[kb + 4 * q + 3][nl];
            __nv_bfloat16 h0 = __float2bfloat16(v0), h1 = __float2bfloat16(v1);
            __nv_bfloat16 h2 = __float2bfloat16(v2), h3 = __float2bfloat16(v3);
            __nv_bfloat162 ph01(h0, h1), ph23(h2, h3);
            __nv_bfloat162 pl01(__float2bfloat16(v0 - __bfloat162float(h0)),
                                __float2bfloat16(v1 - __bfloat162float(h1)));
            __nv_bfloat162 pl23(__float2bfloat16(v2 - __bfloat162float(h2)),
                                __float2bfloat16(v3 - __bfloat162float(h3)));
            *(uint2*)(dhi + obase + 4 * q) =
                make_uint2(*(uint32_t*)&ph01, *(uint32_t*)&ph23);
            *(uint2*)(dlo + obase + 4 * q) =
                make_uint2(*(uint32_t*)&pl01, *(uint32_t*)&pl23);
        }
    }
}

// ---------------------------------------------------------------------------
// HMMA grouped GEMM (R13/R8 core, unchanged): CTA 128x256, BK=64, 512 thr.
// M-tiles from compact table; blockIdx.z selects matrix pair (gate/up).
//   amode 1: arow = token;  amode 0: arow = slot (down, wslot scaling)
// ---------------------------------------------------------------------------
#define GEMM_SMEM (1024 + 2 * 98304)
__global__ void __launch_bounds__(512, 1)
mma_gemm(const __nv_bfloat16* __restrict__ Ahi, const __nv_bfloat16* __restrict__ Alo,
         const __nv_bfloat16* __restrict__ B0eHi, const __nv_bfloat16* __restrict__ B0eLo,
         const __nv_bfloat16* __restrict__ B0sHi, const __nv_bfloat16* __restrict__ B0sLo,
         float* __restrict__ C0,
         const __nv_bfloat16* __restrict__ B1eHi, const __nv_bfloat16* __restrict__ B1eLo,
         const __nv_bfloat16* __restrict__ B1sHi, const __nv_bfloat16* __restrict__ B1sLo,
         float* __restrict__ C1,
         const int* __restrict__ list,
         int amode, const float* __restrict__ wslot) {
    int ty = blockIdx.y;
    int e, m0, cnt;
    bool sh;
    if (ty >= MAXRT) {
        sh = true; e = 0; m0 = (ty - MAXRT) * 128; cnt = NTOK;
    } else {
        if (ty >= g_ntile_rt) return;
        sh = false; e = g_tileE[ty]; m0 = g_tileM[ty]; cnt = g_count[e];
    }
    int mat = blockIdx.z;
    int n0 = blockIdx.x * 256;
    const __nv_bfloat16* BeHi = mat ? B1eHi : B0eHi;
    const __nv_bfloat16* BeLo = mat ? B1eLo : B0eLo;
    const __nv_bfloat16* BsHi = mat ? B1sHi : B0sHi;
    const __nv_bfloat16* BsLo = mat ? B1sLo : B0sLo;
    float* C = mat ? C1 : C0;
    const char* Bh = (const char*)(sh ? BsHi : BeHi + ((size_t)e << 20));
    const char* Bl = (const char*)(sh ? BsLo : BeLo + ((size_t)e << 20));
    const char* Ah = (const char*)Ahi;
    const char* Al = (const char*)Alo;

    extern __shared__ __align__(128) char smem[];
    int*   slotArr = (int*)smem;
    float* wArr    = (float*)(smem + 512);
    uint32_t sb = smem_u32(smem);
    const uint32_t TB = sb + 1024;

    int tid = threadIdx.x, lane = tid & 31, wid = tid >> 5;

    if (tid < 128) {
        int r = m0 + tid;
        int rc = (r < cnt) ? r : (cnt - 1);
        int slot = sh ? (SLOTS + rc) : list[e * CAP + rc];
        slotArr[tid] = slot;
        wArr[tid] = (!sh && wslot) ? wslot[slot] : 1.f;
    }
    __syncthreads();

    int rb = tid >> 3, kc = tid & 7;
    size_t aoff[2]; uint32_t adst[2];
#pragma unroll
    for (int j = 0; j < 2; j++) {
        int r = rb + 64 * j;
        int slot = slotArr[r];
        int arow = amode ? (sh ? (slot - SLOTS) : (slot >> 1)) : slot;
        aoff[j] = ((size_t)arow * 1024 + kc * 8) * 2;
        adst[j] = (uint32_t)(r * 128 + ((kc ^ (r & 7)) * 16));
    }
    size_t boff[4]; uint32_t bdst[4];
#pragma unroll
    for (int j = 0; j < 4; j++) {
        int r = rb + 64 * j;
        boff[j] = ((size_t)(n0 + r) * 1024 + kc * 8) * 2;
        bdst[j] = (uint32_t)(r * 128 + ((kc ^ (r & 7)) * 16));
    }

#define ST(stg, sub) (TB + (stg) * 98304u + \
    ((sub) == 0 ? 0u : (sub) == 1 ? 16384u : (sub) == 2 ? 32768u : 65536u))
#define LOAD_STAGE(kb, stg) do {                                     \
    _Pragma("unroll")                                                \
    for (int j = 0; j < 2; j++) {                                    \
        cp16(ST(stg,0) + adst[j], Ah + aoff[j] + (kb));              \
        cp16(ST(stg,1) + adst[j], Al + aoff[j] + (kb));              \
    }                                                                \
    _Pragma("unroll")                                                \
    for (int j = 0; j < 4; j++) {                                    \
        cp16(ST(stg,2) + bdst[j], Bh + boff[j] + (kb));              \
        cp16(ST(stg,3) + bdst[j], Bl + boff[j] + (kb));              \
    }                                                                \
    cp_commit(); } while (0)

    float acc[4][4][4];
#pragma unroll
    for (int i = 0; i < 4; i++)
#pragma unroll
        for (int j = 0; j < 4; j++)
#pragma unroll
            for (int q = 0; q < 4; q++) acc[i][j][q] = 0.f;

    int warpM = (wid & 1) * 64;
    int warpN = (wid >> 1) * 32;
    int a_r = (lane & 7) + 8 * ((lane >> 3) & 1);
    int a_c = (lane >> 4) & 1;
    int b_r = (lane & 7) + 8 * ((lane >> 4) & 1);
    int b_c = (lane >> 3) & 1;

    LOAD_STAGE(0, 0);

#pragma unroll 1
    for (int s = 0; s < 16; s++) {
        uint32_t stg = s & 1;
        if (s < 15) {
            LOAD_STAGE((size_t)(s + 1) * 128, (s + 1) & 1);
            CP_WAIT(1);
        } else {
            CP_WAIT(0);
        }
        __syncthreads();

#pragma unroll
        for (int kk = 0; kk < 4; kk++) {
            int ac = 2 * kk + a_c;
            int bc = 2 * kk + b_c;
            uint32_t a_hi[4][4], a_lo[4][4], bfr[2][4];
#pragma unroll
            for (int fm = 0; fm < 4; fm++) {
                int r = warpM + fm * 16 + a_r;
                uint32_t off = (uint32_t)(r * 128 + ((ac ^ (r & 7)) * 16));
                ldsm4(a_hi[fm], ST(stg, 0) + off);
                ldsm4(a_lo[fm], ST(stg, 1) + off);
            }
            // phase 1: b_hi -> hi*hi + lo*hi
#pragma unroll
            for (int fb = 0; fb < 2; fb++) {
                int n = warpN + fb * 16 + b_r;
                uint32_t off = (uint32_t)(n * 128 + ((bc ^ (n & 7)) * 16));
                ldsm4(bfr[fb], ST(stg, 2) + off);
            }
#pragma unroll
            for (int fm = 0; fm < 4; fm++)
#pragma unroll
                for (int fn = 0; fn < 4; fn++) {
                    int fb = fn >> 1, sel = (fn & 1) * 2;
                    mma16816(acc[fm][fn], a_hi[fm], bfr[fb][sel], bfr[fb][sel + 1]);
                    mma16816(acc[fm][fn], a_lo[fm], bfr[fb][sel], bfr[fb][sel + 1]);
                }
            // phase 2: b_lo -> hi*lo
#pragma unroll
            for (int fb = 0; fb < 2; fb++) {
                int n = warpN + fb * 16 + b_r;
                uint32_t off = (uint32_t)(n * 128 + ((bc ^ (n & 7)) * 16));
                ldsm4(bfr[fb], ST(stg, 3) + off);
            }
#pragma unroll
            for (int fm = 0; fm < 4; fm++)
#pragma unroll
                for (int fn = 0; fn < 4; fn++) {
                    int fb = fn >> 1, sel = (fn & 1) * 2;
                    mma16816(acc[fm][fn], a_hi[fm], bfr[fb][sel], bfr[fb][sel + 1]);
                }
        }
        __syncthreads();
    }

    // ---- epilogue: scatter scaled rows ----
#pragma unroll
    for (int fm = 0; fm < 4; fm++) {
        int rloc0 = warpM + fm * 16 + (lane >> 2);
        int rloc1 = rloc0 + 8;
        bool v0 = (m0 + rloc0) < cnt, v1 = (m0 + rloc1) < cnt;
        int s0 = slotArr[rloc0], s1 = slotArr[rloc1];
        float w0 = wArr[rloc0], w1 = wArr[rloc1];
        float* c0p = C + (size_t)s0 * 1024 + n0 + (lane & 3) * 2;
        float* c1p = C + (size_t)s1 * 1024 + n0 + (lane & 3) * 2;
#pragma unroll
        for (int fn = 0; fn < 4; fn++) {
            int coff = warpN + fn * 8;
            if (v0) *(float2*)(c0p + coff) =
                make_float2(acc[fm][fn][0] * w0, acc[fm][fn][1] * w0);
            if (v1) *(float2*)(c1p + coff) =
                make_float2(acc[fm][fn][2] * w1, acc[fm][fn][3] * w1);
        }
    }
#undef LOAD_STAGE
#undef ST
}

// ---------------------------------------------------------------------------
// h = silu(g) * u -> split bf16 (coalesced streams)
// ---------------------------------------------------------------------------
__global__ void silumul_kernel() {
    size_t i = (size_t)blockIdx.x * 256 + threadIdx.x;  // float4 idx
    float4 g = ((const float4*)g_gbuf)[i];
    float4 u = ((const float4*)g_ubuf)[i];
    float h0 = g.x / (1.f + expf(-g.x)) * u.x;
    float h1 = g.y / (1.f + expf(-g.y)) * u.y;
    float h2 = g.z / (1.f + expf(-g.z)) * u.z;
    float h3 = g.w / (1.f + expf(-g.w)) * u.w;
    __nv_bfloat16 a0 = __float2bfloat16(h0), a1 = __float2bfloat16(h1);
    __nv_bfloat16 a2 = __float2bfloat16(h2), a3 = __float2bfloat16(h3);
    __nv_bfloat162* HI = (__nv_bfloat162*)g_Hhi;
    __nv_bfloat162* LO = (__nv_bfloat162*)g_Hlo;
    HI[2 * i]     = __nv_bfloat162(a0, a1);
    HI[2 * i + 1] = __nv_bfloat162(a2, a3);
    LO[2 * i]     = __nv_bfloat162(__float2bfloat16(h0 - __bfloat162float(a0)),
                                   __float2bfloat16(h1 - __bfloat162float(a1)));
    LO[2 * i + 1] = __nv_bfloat162(__float2bfloat16(h2 - __bfloat162float(a2)),
                                   __float2bfloat16(h3 - __bfloat162float(a3)));
}

// ---------------------------------------------------------------------------
// out[n] = shared + routed0 + routed1
// ---------------------------------------------------------------------------
__global__ void final_kernel(float* __restrict__ out) {
    size_t i = (size_t)blockIdx.x * 256 + threadIdx.x;
    size_t n = i / (DIMD / 4);
    size_t c = i % (DIMD / 4);
    const float4* ysh = (const float4*)(g_ybuf + (size_t)(SLOTS + n) * DIMD);
    const float4* y0  = (const float4*)(g_ybuf + (size_t)(2 * n) * DIMD);
    const float4* y1  = (const float4*)(g_ybuf + (size_t)(2 * n + 1) * DIMD);
    float4 a = ysh[c], b = y0[c], d = y1[c];
    ((float4*)out)[i] = make_float4(a.x + b.x + d.x, a.y + b.y + d.y,
                                    a.z + b.z + d.z, a.w + b.w + d.w);
}

// ---------------------------------------------------------------------------
extern "C" void kernel_launch(void* const* d_in, const int* in_sizes, int n_in,
                              void* d_out, int out_size) {
    const float* x  = (const float*)d_in[0];
    const float* sg = (const float*)d_in[1];
    const float* su = (const float*)d_in[2];
    const float* sd = (const float*)d_in[3];
    const float* Wg = (const float*)d_in[4];
    const float* Wu = (const float*)d_in[5];
    const float* Wd = (const float*)d_in[6];
    const float* Wr = (const float*)d_in[7];
    const float* lt = (const float*)d_in[8];
    const int*   li = (const int*)d_in[9];
    float* out = (float*)d_out;

    cudaFuncSetAttribute(mma_gemm, cudaFuncAttributeMaxDynamicSharedMemorySize,
                         GEMM_SMEM);

    float *gbuf, *ubuf, *ybuf, *ws;
    int *list;
    __nv_bfloat16 *Xhi, *Xlo, *Hhi, *Hlo;
    __nv_bfloat16 *WgThi, *WgTlo, *WuThi, *WuTlo, *WdThi, *WdTlo;
    __nv_bfloat16 *sgThi, *sgTlo, *suThi, *suTlo, *sdThi, *sdTlo;
    cudaGetSymbolAddress((void**)&gbuf,  g_gbuf);
    cudaGetSymbolAddress((void**)&ubuf,  g_ubuf);
    cudaGetSymbolAddress((void**)&ybuf,  g_ybuf);
    cudaGetSymbolAddress((void**)&ws,    g_wslot);
    cudaGetSymbolAddress((void**)&list,  g_list);
    cudaGetSymbolAddress((void**)&Xhi,   g_Xhi);
    cudaGetSymbolAddress((void**)&Xlo,   g_Xlo);
    cudaGetSymbolAddress((void**)&Hhi,   g_Hhi);
    cudaGetSymbolAddress((void**)&Hlo,   g_Hlo);
    cudaGetSymbolAddress((void**)&WgThi, g_WgThi);
    cudaGetSymbolAddress((void**)&WgTlo, g_WgTlo);
    cudaGetSymbolAddress((void**)&WuThi, g_WuThi);
    cudaGetSymbolAddress((void**)&WuTlo, g_WuTlo);
    cudaGetSymbolAddress((void**)&WdThi, g_WdThi);
    cudaGetSymbolAddress((void**)&WdTlo, g_WdTlo);
    cudaGetSymbolAddress((void**)&sgThi, g_sgThi);
    cudaGetSymbolAddress((void**)&sgTlo, g_sgTlo);
    cudaGetSymbolAddress((void**)&suThi, g_suThi);
    cudaGetSymbolAddress((void**)&suTlo, g_suTlo);
    cudaGetSymbolAddress((void**)&sdThi, g_sdThi);
    cudaGetSymbolAddress((void**)&sdTlo, g_sdTlo);

    // (v0) router (incl. loop bias)
    router_kernel<<<NTOK / 8, 256>>>(x, Wr, lt, li);
    // (v1) dispatch
    dispatch_kernel<<<NEXP, 256>>>();
    // (v2) prep: 27 transposes (64x64) + x split + tile table
    TPArgs tp;
    tp.s[0] = Wg; tp.h[0] = WgThi; tp.l[0] = WgTlo;
    tp.s[1] = Wu; tp.h[1] = WuThi; tp.l[1] = WuTlo;
    tp.s[2] = Wd; tp.h[2] = WdThi; tp.l[2] = WdTlo;
    tp.s[3] = sg; tp.h[3] = sgThi; tp.l[3] = sgTlo;
    tp.s[4] = su; tp.h[4] = suThi; tp.l[4] = suTlo;
    tp.s[5] = sd; tp.h[5] = sdThi; tp.l[5] = sdTlo;
    prep_all_kernel<<<dim3(16, 16, 31), 256>>>(tp, x);

    // (v3) gate+up fused over compact tile table  <- ncu capture slot
    dim3 ggu(4, NTILEY, 2);
    mma_gemm<<<ggu, 512, GEMM_SMEM>>>(Xhi, Xlo,
                                      WgThi, WgTlo, sgThi, sgTlo, gbuf,
                                      WuThi, WuTlo, suThi, suTlo, ubuf,
                                      list, 1, nullptr);
    // (v4) h = silu(g)*u (split)
    silumul_kernel<<<(int)(((size_t)TOT * 1024 / 4) / 256), 256>>>();
    // (v5) down
    dim3 gd(4, NTILEY, 1);
    mma_gemm<<<gd, 512, GEMM_SMEM>>>(Hhi, Hlo,
                                     WdThi, WdTlo, sdThi, sdTlo, ybuf,
                                     WdThi, WdTlo, sdThi, sdTlo, ybuf,
                                     list, 0, ws);
    // (v6) combine
    final_kernel<<<(NTOK * DIMD / 4) / 256, 256>>>(out);
}

// round 16
// speedup vs baseline: 1.0342x; 1.0342x over previous
#include <cuda_runtime.h>
#include <cuda_bf16.h>
#include <cstdint>
#include <math.h>

// ===========================================================================
// MoE layer via mma.sync m16n8k16 bf16 (compute_103-safe). bf16-split 3-MMA
// (hi*hi + lo*hi + hi*lo), fp32 accum -> ~1e-5 rel err.
// R15: R13 structure (separate rconst/router/convert_x; compact tile table;
// gate+up one launch) + R14's fast 64x64 float4 transpose as its own launch.
// Router merge is a confirmed anti-pattern (+21us twice) - not repeated.
// ===========================================================================

#define DIMD   1024
#define NTOK   4096
#define NEXP   8
#define CAP    8192
#define SLOTS  (NTOK * 2)
#define TOT    (SLOTS + NTOK)
#define MAXRT  72                  // max routed M-tiles
#define NTILEY (MAXRT + 32)        // + 32 shared M-tiles

// ---------------- static scratch ----------------
__device__ float g_gbuf[(size_t)TOT * 1024];
__device__ float g_ubuf[(size_t)TOT * 1024];
__device__ float g_ybuf[(size_t)TOT * 1024];
__device__ __nv_bfloat16 g_Xhi[(size_t)NTOK * 1024];
__device__ __nv_bfloat16 g_Xlo[(size_t)NTOK * 1024];
__device__ __nv_bfloat16 g_Hhi[(size_t)TOT * 1024];
__device__ __nv_bfloat16 g_Hlo[(size_t)TOT * 1024];
// transposed ([out][in] = [n][k]) split weights
__device__ __nv_bfloat16 g_WgThi[(size_t)NEXP << 20];
__device__ __nv_bfloat16 g_WgTlo[(size_t)NEXP << 20];
__device__ __nv_bfloat16 g_WuThi[(size_t)NEXP << 20];
__device__ __nv_bfloat16 g_WuTlo[(size_t)NEXP << 20];
__device__ __nv_bfloat16 g_WdThi[(size_t)NEXP << 20];
__device__ __nv_bfloat16 g_WdTlo[(size_t)NEXP << 20];
__device__ __nv_bfloat16 g_sgThi[1 << 20];
__device__ __nv_bfloat16 g_sgTlo[1 << 20];
__device__ __nv_bfloat16 g_suThi[1 << 20];
__device__ __nv_bfloat16 g_suTlo[1 << 20];
__device__ __nv_bfloat16 g_sdThi[1 << 20];
__device__ __nv_bfloat16 g_sdTlo[1 << 20];
__device__ int   g_list[NEXP * CAP];
__device__ int   g_count[NEXP];
__device__ int   g_expert_of[SLOTS];
__device__ float g_wslot[SLOTS];
__device__ float g_rconst[NEXP];
__device__ int   g_tileE[MAXRT];
__device__ int   g_tileM[MAXRT];
__device__ int   g_ntile_rt;

// ---------------- helpers ----------------
__device__ __forceinline__ uint32_t smem_u32(const void* p) {
    uint32_t a;
    asm("{ .reg .u64 t; cvta.to.shared.u64 t, %1; cvt.u32.u64 %0, t; }"
        : "=r"(a) : "l"(p));
    return a;
}
__device__ __forceinline__ void cp16(uint32_t dst, const void* src) {
    asm volatile("cp.async.cg.shared.global [%0], [%1], 16;" :: "r"(dst), "l"(src));
}
__device__ __forceinline__ void cp_commit() {
    asm volatile("cp.async.commit_group;" ::: "memory");
}
#define CP_WAIT(n) asm volatile("cp.async.wait_group %0;" :: "n"(n) : "memory")

__device__ __forceinline__ void ldsm4(uint32_t* r, uint32_t addr) {
    asm volatile("ldmatrix.sync.aligned.m8n8.x4.shared.b16 {%0,%1,%2,%3}, [%4];"
        : "=r"(r[0]), "=r"(r[1]), "=r"(r[2]), "=r"(r[3]) : "r"(addr));
}
__device__ __forceinline__ void mma16816(float* c, const uint32_t* a,
                                         uint32_t b0, uint32_t b1) {
    asm volatile(
        "mma.sync.aligned.m16n8k16.row.col.f32.bf16.bf16.f32 "
        "{%0,%1,%2,%3}, {%4,%5,%6,%7}, {%8,%9}, {%0,%1,%2,%3};"
        : "+f"(c[0]), "+f"(c[1]), "+f"(c[2]), "+f"(c[3])
        : "r"(a[0]), "r"(a[1]), "r"(a[2]), "r"(a[3]), "r"(b0), "r"(b1));
}

// ---------------------------------------------------------------------------
// router bias constants
// ---------------------------------------------------------------------------
__global__ void rconst_kernel(const float* __restrict__ Wr,
                              const float* __restrict__ loop_table,
                              const int* __restrict__ loop_idx) {
    __shared__ float red[256][NEXP];
    int li = loop_idx[0];
    float acc[NEXP];
#pragma unroll
    for (int e = 0; e < NEXP; e++) acc[e] = 0.f;
    for (int d = threadIdx.x; d < DIMD; d += 256) {
        float lv = loop_table[(size_t)li * DIMD + d];
        const float* wr = Wr + (size_t)(DIMD + d) * NEXP;
#pragma unroll
        for (int e = 0; e < NEXP; e++) acc[e] += lv * wr[e];
    }
#pragma unroll
    for (int e = 0; e < NEXP; e++) red[threadIdx.x][e] = acc[e];
    __syncthreads();
    if (threadIdx.x < NEXP) {
        float s = 0.f;
        for (int i = 0; i < 256; i++) s += red[i][threadIdx.x];
        g_rconst[threadIdx.x] = s;
    }
}

// ---------------------------------------------------------------------------
// router: one warp per token, stable top-2
// ---------------------------------------------------------------------------
__global__ void router_kernel(const float* __restrict__ x,
                              const float* __restrict__ Wr) {
    int warp = threadIdx.x >> 5, lane = threadIdx.x & 31;
    int n = blockIdx.x * 8 + warp;
    if (n >= NTOK) return;
    const float* xr = x + (size_t)n * DIMD;
    float acc[NEXP];
#pragma unroll
    for (int e = 0; e < NEXP; e++) acc[e] = 0.f;
    for (int d = lane; d < DIMD; d += 32) {
        float xv = xr[d];
        const float* wr = Wr + (size_t)d * NEXP;
#pragma unroll
        for (int e = 0; e < NEXP; e++) acc[e] += xv * wr[e];
    }
#pragma unroll
    for (int e = 0; e < NEXP; e++)
#pragma unroll
        for (int off = 16; off > 0; off >>= 1)
            acc[e] += __shfl_down_sync(0xffffffffu, acc[e], off);
    if (lane == 0) {
        float p[NEXP];
#pragma unroll
        for (int e = 0; e < NEXP; e++)
            p[e] = 1.f / (1.f + expf(-(acc[e] + g_rconst[e])));
        float b1 = -1.f; int i1 = 0;
#pragma unroll
        for (int e = 0; e < NEXP; e++) if (p[e] > b1) { b1 = p[e]; i1 = e; }
        float b2 = -1.f; int i2 = 0;
#pragma unroll
        for (int e = 0; e < NEXP; e++)
            if (e != i1 && p[e] > b2) { b2 = p[e]; i2 = e; }
        g_expert_of[2 * n]     = i1;  g_wslot[2 * n]     = b1;
        g_expert_of[2 * n + 1] = i2;  g_wslot[2 * n + 1] = b2;
    }
}

// ---------------------------------------------------------------------------
// dispatch: ordered per-expert slot lists
// ---------------------------------------------------------------------------
__global__ void dispatch_kernel() {
    int e = blockIdx.x;
    __shared__ int warp_tot[8];
    __shared__ int warp_off[8];
    __shared__ int s_base;
    if (threadIdx.x == 0) s_base = 0;
    __syncthreads();
    int lane = threadIdx.x & 31, w = threadIdx.x >> 5;
    for (int s0 = 0; s0 < SLOTS; s0 += 256) {
        int s = s0 + threadIdx.x;
        bool f = (g_expert_of[s] == e);
        unsigned bal = __ballot_sync(0xffffffffu, f);
        if (lane == 0) warp_tot[w] = __popc(bal);
        __syncthreads();
        if (threadIdx.x == 0) {
            int a = s_base;
            for (int i = 0; i < 8; i++) { warp_off[i] = a; a += warp_tot[i]; }
            s_base = a;
        }
        __syncthreads();
        if (f) {
            int pos = warp_off[w] + __popc(bal & ((1u << lane) - 1u));
            g_list[e * CAP + pos] = s;
        }
        __syncthreads();
    }
    if (threadIdx.x == 0) g_count[e] = s_base;
}

// ---------------------------------------------------------------------------
// build compact routed M-tile table
// ---------------------------------------------------------------------------
__global__ void build_tiles_kernel() {
    __shared__ int off[NEXP];
    if (threadIdx.x == 0) {
        int a = 0;
        for (int e = 0; e < NEXP; e++) {
            off[e] = a;
            a += (g_count[e] + 127) >> 7;
        }
        g_ntile_rt = a;
    }
    __syncthreads();
    if (threadIdx.x < NEXP) {
        int e = threadIdx.x;
        int nt = (g_count[e] + 127) >> 7;
        int o = off[e];
        for (int t = 0; t < nt; t++) {
            g_tileE[o + t] = e;
            g_tileM[o + t] = t * 128;
        }
    }
}

// ---------------------------------------------------------------------------
// x -> split bf16 hi/lo
// ---------------------------------------------------------------------------
__global__ void convert_x_kernel(const float* __restrict__ x) {
    size_t i = (size_t)blockIdx.x * 256 + threadIdx.x;  // float4 idx
    float4 v = ((const float4*)x)[i];
    __nv_bfloat16 h0 = __float2bfloat16(v.x), h1 = __float2bfloat16(v.y);
    __nv_bfloat16 h2 = __float2bfloat16(v.z), h3 = __float2bfloat16(v.w);
    __nv_bfloat162* HI = (__nv_bfloat162*)g_Xhi;
    __nv_bfloat162* LO = (__nv_bfloat162*)g_Xlo;
    HI[2 * i]     = __nv_bfloat162(h0, h1);
    HI[2 * i + 1] = __nv_bfloat162(h2, h3);
    LO[2 * i]     = __nv_bfloat162(__float2bfloat16(v.x - __bfloat162float(h0)),
                                   __float2bfloat16(v.y - __bfloat162float(h1)));
    LO[2 * i + 1] = __nv_bfloat162(__float2bfloat16(v.z - __bfloat162float(h2)),
                                   __float2bfloat16(v.w - __bfloat162float(h3)));
}

// ---------------------------------------------------------------------------
// fast 64x64 weight transpose + split (float4 loads, uint2 stores)
// grid (16, 16, 27), 256 threads
// ---------------------------------------------------------------------------
struct TPArgs {
    const float* s[6];
    __nv_bfloat16* h[6];
    __nv_bfloat16* l[6];
};
__global__ void transpose_all_kernel(TPArgs tp) {
    __shared__ float tile[64][65];
    int z = blockIdx.z;
    int tid = threadIdx.x;
    int g, m;
    if (z < 24) { g = z >> 3; m = z & 7; } else { g = 3 + (z - 24); m = 0; }
    size_t mbase = (size_t)m << 20;
    const float* S = tp.s[g] + mbase;
    __nv_bfloat16* dhi = tp.h[g] + mbase;
    __nv_bfloat16* dlo = tp.l[g] + mbase;
    int k0 = blockIdx.y * 64, n0 = blockIdx.x * 64;

    // load: thread -> rows (tid>>4)+16i, float4 cols (tid&15)*4
    int lr = tid >> 4, lc = (tid & 15) * 4;
#pragma unroll
    for (int i = 0; i < 4; i++) {
        int r = lr + 16 * i;
        float4 v = *(const float4*)(S + (size_t)(k0 + r) * 1024 + n0 + lc);
        tile[r][lc + 0] = v.x;
        tile[r][lc + 1] = v.y;
        tile[r][lc + 2] = v.z;
        tile[r][lc + 3] = v.w;
    }
    __syncthreads();

    // store: two passes of 32 out-rows; thread -> row (tid>>3)+32p, 8 k's
#pragma unroll
    for (int p = 0; p < 2; p++) {
        int nl = (tid >> 3) + 32 * p;
        int kb = (tid & 7) * 8;
        size_t obase = (size_t)(n0 + nl) * 1024 + k0 + kb;
#pragma unroll
        for (int q = 0; q < 2; q++) {
            float v0 = tile[kb + 4 * q + 0][nl];
            float v1 = tile[kb + 4 * q + 1][nl];
            float v2 = tile[kb + 4 * q + 2][nl];
            float v3 = tile[kb + 4 * q + 3][nl];
            __nv_bfloat16 h0 = __float2bfloat16(v0), h1 = __float2bfloat16(v1);
            __nv_bfloat16 h2 = __float2bfloat16(v2), h3 = __float2bfloat16(v3);
            __nv_bfloat162 ph01(h0, h1), ph23(h2, h3);
            __nv_bfloat162 pl01(__float2bfloat16(v0 - __bfloat162float(h0)),
                                __float2bfloat16(v1 - __bfloat162float(h1)));
            __nv_bfloat162 pl23(__float2bfloat16(v2 - __bfloat162float(h2)),
                                __float2bfloat16(v3 - __bfloat162float(h3)));
            *(uint2*)(dhi + obase + 4 * q) =
                make_uint2(*(uint32_t*)&ph01, *(uint32_t*)&ph23);
            *(uint2*)(dlo + obase + 4 * q) =
                make_uint2(*(uint32_t*)&pl01, *(uint32_t*)&pl23);
        }
    }
}

// ---------------------------------------------------------------------------
// HMMA grouped GEMM (R13/R8 core, unchanged): CTA 128x256, BK=64, 512 thr.
// M-tiles from compact table; blockIdx.z selects matrix pair (gate/up).
//   amode 1: arow = token;  amode 0: arow = slot (down, wslot scaling)
// ---------------------------------------------------------------------------
#define GEMM_SMEM (1024 + 2 * 98304)
__global__ void __launch_bounds__(512, 1)
mma_gemm(const __nv_bfloat16* __restrict__ Ahi, const __nv_bfloat16* __restrict__ Alo,
         const __nv_bfloat16* __restrict__ B0eHi, const __nv_bfloat16* __restrict__ B0eLo,
         const __nv_bfloat16* __restrict__ B0sHi, const __nv_bfloat16* __restrict__ B0sLo,
         float* __restrict__ C0,
         const __nv_bfloat16* __restrict__ B1eHi, const __nv_bfloat16* __restrict__ B1eLo,
         const __nv_bfloat16* __restrict__ B1sHi, const __nv_bfloat16* __restrict__ B1sLo,
         float* __restrict__ C1,
         const int* __restrict__ list,
         int amode, const float* __restrict__ wslot) {
    int ty = blockIdx.y;
    int e, m0, cnt;
    bool sh;
    if (ty >= MAXRT) {
        sh = true; e = 0; m0 = (ty - MAXRT) * 128; cnt = NTOK;
    } else {
        if (ty >= g_ntile_rt) return;
        sh = false; e = g_tileE[ty]; m0 = g_tileM[ty]; cnt = g_count[e];
    }
    int mat = blockIdx.z;
    int n0 = blockIdx.x * 256;
    const __nv_bfloat16* BeHi = mat ? B1eHi : B0eHi;
    const __nv_bfloat16* BeLo = mat ? B1eLo : B0eLo;
    const __nv_bfloat16* BsHi = mat ? B1sHi : B0sHi;
    const __nv_bfloat16* BsLo = mat ? B1sLo : B0sLo;
    float* C = mat ? C1 : C0;
    const char* Bh = (const char*)(sh ? BsHi : BeHi + ((size_t)e << 20));
    const char* Bl = (const char*)(sh ? BsLo : BeLo + ((size_t)e << 20));
    const char* Ah = (const char*)Ahi;
    const char* Al = (const char*)Alo;

    extern __shared__ __align__(128) char smem[];
    int*   slotArr = (int*)smem;
    float* wArr    = (float*)(smem + 512);
    uint32_t sb = smem_u32(smem);
    const uint32_t TB = sb + 1024;

    int tid = threadIdx.x, lane = tid & 31, wid = tid >> 5;

    if (tid < 128) {
        int r = m0 + tid;
        int rc = (r < cnt) ? r : (cnt - 1);
        int slot = sh ? (SLOTS + rc) : list[e * CAP + rc];
        slotArr[tid] = slot;
        wArr[tid] = (!sh && wslot) ? wslot[slot] : 1.f;
    }
    __syncthreads();

    int rb = tid >> 3, kc = tid & 7;
    size_t aoff[2]; uint32_t adst[2];
#pragma unroll
    for (int j = 0; j < 2; j++) {
        int r = rb + 64 * j;
        int slot = slotArr[r];
        int arow = amode ? (sh ? (slot - SLOTS) : (slot >> 1)) : slot;
        aoff[j] = ((size_t)arow * 1024 + kc * 8) * 2;
        adst[j] = (uint32_t)(r * 128 + ((kc ^ (r & 7)) * 16));
    }
    size_t boff[4]; uint32_t bdst[4];
#pragma unroll
    for (int j = 0; j < 4; j++) {
        int r = rb + 64 * j;
        boff[j] = ((size_t)(n0 + r) * 1024 + kc * 8) * 2;
        bdst[j] = (uint32_t)(r * 128 + ((kc ^ (r & 7)) * 16));
    }

#define ST(stg, sub) (TB + (stg) * 98304u + \
    ((sub) == 0 ? 0u : (sub) == 1 ? 16384u : (sub) == 2 ? 32768u : 65536u))
#define LOAD_STAGE(kb, stg) do {                                     \
    _Pragma("unroll")                                                \
    for (int j = 0; j < 2; j++) {                                    \
        cp16(ST(stg,0) + adst[j], Ah + aoff[j] + (kb));              \
        cp16(ST(stg,1) + adst[j], Al + aoff[j] + (kb));              \
    }                                                                \
    _Pragma("unroll")                                                \
    for (int j = 0; j < 4; j++) {                                    \
        cp16(ST(stg,2) + bdst[j], Bh + boff[j] + (kb));              \
        cp16(ST(stg,3) + bdst[j], Bl + boff[j] + (kb));              \
    }                                                                \
    cp_commit(); } while (0)

    float acc[4][4][4];
#pragma unroll
    for (int i = 0; i < 4; i++)
#pragma unroll
        for (int j = 0; j < 4; j++)
#pragma unroll
            for (int q = 0; q < 4; q++) acc[i][j][q] = 0.f;

    int warpM = (wid & 1) * 64;
    int warpN = (wid >> 1) * 32;
    int a_r = (lane & 7) + 8 * ((lane >> 3) & 1);
    int a_c = (lane >> 4) & 1;
    int b_r = (lane & 7) + 8 * ((lane >> 4) & 1);
    int b_c = (lane >> 3) & 1;

    LOAD_STAGE(0, 0);

#pragma unroll 1
    for (int s = 0; s < 16; s++) {
        uint32_t stg = s & 1;
        if (s < 15) {
            LOAD_STAGE((size_t)(s + 1) * 128, (s + 1) & 1);
            CP_WAIT(1);
        } else {
            CP_WAIT(0);
        }
        __syncthreads();

#pragma unroll
        for (int kk = 0; kk < 4; kk++) {
            int ac = 2 * kk + a_c;
            int bc = 2 * kk + b_c;
            uint32_t a_hi[4][4], a_lo[4][4], bfr[2][4];
#pragma unroll
            for (int fm = 0; fm < 4; fm++) {
                int r = warpM + fm * 16 + a_r;
                uint32_t off = (uint32_t)(r * 128 + ((ac ^ (r & 7)) * 16));
                ldsm4(a_hi[fm], ST(stg, 0) + off);
                ldsm4(a_lo[fm], ST(stg, 1) + off);
            }
            // phase 1: b_hi -> hi*hi + lo*hi
#pragma unroll
            for (int fb = 0; fb < 2; fb++) {
                int n = warpN + fb * 16 + b_r;
                uint32_t off = (uint32_t)(n * 128 + ((bc ^ (n & 7)) * 16));
                ldsm4(bfr[fb], ST(stg, 2) + off);
            }
#pragma unroll
            for (int fm = 0; fm < 4; fm++)
#pragma unroll
                for (int fn = 0; fn < 4; fn++) {
                    int fb = fn >> 1, sel = (fn & 1) * 2;
                    mma16816(acc[fm][fn], a_hi[fm], bfr[fb][sel], bfr[fb][sel + 1]);
                    mma16816(acc[fm][fn], a_lo[fm], bfr[fb][sel], bfr[fb][sel + 1]);
                }
            // phase 2: b_lo -> hi*lo
#pragma unroll
            for (int fb = 0; fb < 2; fb++) {
                int n = warpN + fb * 16 + b_r;
                uint32_t off = (uint32_t)(n * 128 + ((bc ^ (n & 7)) * 16));
                ldsm4(bfr[fb], ST(stg, 3) + off);
            }
#pragma unroll
            for (int fm = 0; fm < 4; fm++)
#pragma unroll
                for (int fn = 0; fn < 4; fn++) {
                    int fb = fn >> 1, sel = (fn & 1) * 2;
                    mma16816(acc[fm][fn], a_hi[fm], bfr[fb][sel], bfr[fb][sel + 1]);
                }
        }
        __syncthreads();
    }

    // ---- epilogue: scatter scaled rows ----
#pragma unroll
    for (int fm = 0; fm < 4; fm++) {
        int rloc0 = warpM + fm * 16 + (lane >> 2);
        int rloc1 = rloc0 + 8;
        bool v0 = (m0 + rloc0) < cnt, v1 = (m0 + rloc1) < cnt;
        int s0 = slotArr[rloc0], s1 = slotArr[rloc1];
        float w0 = wArr[rloc0], w1 = wArr[rloc1];
        float* c0p = C + (size_t)s0 * 1024 + n0 + (lane & 3) * 2;
        float* c1p = C + (size_t)s1 * 1024 + n0 + (lane & 3) * 2;
#pragma unroll
        for (int fn = 0; fn < 4; fn++) {
            int coff = warpN + fn * 8;
            if (v0) *(float2*)(c0p + coff) =
                make_float2(acc[fm][fn][0] * w0, acc[fm][fn][1] * w0);
            if (v1) *(float2*)(c1p + coff) =
                make_float2(acc[fm][fn][2] * w1, acc[fm][fn][3] * w1);
        }
    }
#undef LOAD_STAGE
#undef ST
}

// ---------------------------------------------------------------------------
// h = silu(g) * u -> split bf16 (coalesced streams)
// ---------------------------------------------------------------------------
__global__ void silumul_kernel() {
    size_t i = (size_t)blockIdx.x * 256 + threadIdx.x;  // float4 idx
    float4 g = ((const float4*)g_gbuf)[i];
    float4 u = ((const float4*)g_ubuf)[i];
    float h0 = g.x / (1.f + expf(-g.x)) * u.x;
    float h1 = g.y / (1.f + expf(-g.y)) * u.y;
    float h2 = g.z / (1.f + expf(-g.z)) * u.z;
    float h3 = g.w / (1.f + expf(-g.w)) * u.w;
    __nv_bfloat16 a0 = __float2bfloat16(h0), a1 = __float2bfloat16(h1);
    __nv_bfloat16 a2 = __float2bfloat16(h2), a3 = __float2bfloat16(h3);
    __nv_bfloat162* HI = (__nv_bfloat162*)g_Hhi;
    __nv_bfloat162* LO = (__nv_bfloat162*)g_Hlo;
    HI[2 * i]     = __nv_bfloat162(a0, a1);
    HI[2 * i + 1] = __nv_bfloat162(a2, a3);
    LO[2 * i]     = __nv_bfloat162(__float2bfloat16(h0 - __bfloat162float(a0)),
                                   __float2bfloat16(h1 - __bfloat162float(a1)));
    LO[2 * i + 1] = __nv_bfloat162(__float2bfloat16(h2 - __bfloat162float(a2)),
                                   __float2bfloat16(h3 - __bfloat162float(a3)));
}

// ---------------------------------------------------------------------------
// out[n] = shared + routed0 + routed1
// ---------------------------------------------------------------------------
__global__ void final_kernel(float* __restrict__ out) {
    size_t i = (size_t)blockIdx.x * 256 + threadIdx.x;
    size_t n = i / (DIMD / 4);
    size_t c = i % (DIMD / 4);
    const float4* ysh = (const float4*)(g_ybuf + (size_t)(SLOTS + n) * DIMD);
    const float4* y0  = (const float4*)(g_ybuf + (size_t)(2 * n) * DIMD);
    const float4* y1  = (const float4*)(g_ybuf + (size_t)(2 * n + 1) * DIMD);
    float4 a = ysh[c], b = y0[c], d = y1[c];
    ((float4*)out)[i] = make_float4(a.x + b.x + d.x, a.y + b.y + d.y,
                                    a.z + b.z + d.z, a.w + b.w + d.w);
}

// ---------------------------------------------------------------------------
extern "C" void kernel_launch(void* const* d_in, const int* in_sizes, int n_in,
                              void* d_out, int out_size) {
    const float* x  = (const float*)d_in[0];
    const float* sg = (const float*)d_in[1];
    const float* su = (const float*)d_in[2];
    const float* sd = (const float*)d_in[3];
    const float* Wg = (const float*)d_in[4];
    const float* Wu = (const float*)d_in[5];
    const float* Wd = (const float*)d_in[6];
    const float* Wr = (const float*)d_in[7];
    const float* lt = (const float*)d_in[8];
    const int*   li = (const int*)d_in[9];
    float* out = (float*)d_out;

    cudaFuncSetAttribute(mma_gemm, cudaFuncAttributeMaxDynamicSharedMemorySize,
                         GEMM_SMEM);

    float *gbuf, *ubuf, *ybuf, *ws;
    int *list;
    __nv_bfloat16 *Xhi, *Xlo, *Hhi, *Hlo;
    __nv_bfloat16 *WgThi, *WgTlo, *WuThi, *WuTlo, *WdThi, *WdTlo;
    __nv_bfloat16 *sgThi, *sgTlo, *suThi, *suTlo, *sdThi, *sdTlo;
    cudaGetSymbolAddress((void**)&gbuf,  g_gbuf);
    cudaGetSymbolAddress((void**)&ubuf,  g_ubuf);
    cudaGetSymbolAddress((void**)&ybuf,  g_ybuf);
    cudaGetSymbolAddress((void**)&ws,    g_wslot);
    cudaGetSymbolAddress((void**)&list,  g_list);
    cudaGetSymbolAddress((void**)&Xhi,   g_Xhi);
    cudaGetSymbolAddress((void**)&Xlo,   g_Xlo);
    cudaGetSymbolAddress((void**)&Hhi,   g_Hhi);
    cudaGetSymbolAddress((void**)&Hlo,   g_Hlo);
    cudaGetSymbolAddress((void**)&WgThi, g_WgThi);
    cudaGetSymbolAddress((void**)&WgTlo, g_WgTlo);
    cudaGetSymbolAddress((void**)&WuThi, g_WuThi);
    cudaGetSymbolAddress((void**)&WuTlo, g_WuTlo);
    cudaGetSymbolAddress((void**)&WdThi, g_WdThi);
    cudaGetSymbolAddress((void**)&WdTlo, g_WdTlo);
    cudaGetSymbolAddress((void**)&sgThi, g_sgThi);
    cudaGetSymbolAddress((void**)&sgTlo, g_sgTlo);
    cudaGetSymbolAddress((void**)&suThi, g_suThi);
    cudaGetSymbolAddress((void**)&suTlo, g_suTlo);
    cudaGetSymbolAddress((void**)&sdThi, g_sdThi);
    cudaGetSymbolAddress((void**)&sdTlo, g_sdTlo);

    // routing
    rconst_kernel<<<1, 256>>>(Wr, lt, li);
    router_kernel<<<NTOK / 8, 256>>>(x, Wr);
    dispatch_kernel<<<NEXP, 256>>>();
    build_tiles_kernel<<<1, 32>>>();
    // precision splits
    convert_x_kernel<<<(NTOK * 1024 / 4) / 256, 256>>>(x);
    TPArgs tp;
    tp.s[0] = Wg; tp.h[0] = WgThi; tp.l[0] = WgTlo;
    tp.s[1] = Wu; tp.h[1] = WuThi; tp.l[1] = WuTlo;
    tp.s[2] = Wd; tp.h[2] = WdThi; tp.l[2] = WdTlo;
    tp.s[3] = sg; tp.h[3] = sgThi; tp.l[3] = sgTlo;
    tp.s[4] = su; tp.h[4] = suThi; tp.l[4] = suTlo;
    tp.s[5] = sd; tp.h[5] = sdThi; tp.l[5] = sdTlo;
    transpose_all_kernel<<<dim3(16, 16, 27), 256>>>(tp);

    // gate+up fused launch over compact tile table (z: 0 gate, 1 up)
    dim3 ggu(4, NTILEY, 2);
    mma_gemm<<<ggu, 512, GEMM_SMEM>>>(Xhi, Xlo,
                                      WgThi, WgTlo, sgThi, sgTlo, gbuf,
                                      WuThi, WuTlo, suThi, suTlo, ubuf,
                                      list, 1, nullptr);
    // h = silu(g)*u (split)
    silumul_kernel<<<(int)(((size_t)TOT * 1024 / 4) / 256), 256>>>();
    // down
    dim3 gd(4, NTILEY, 1);
    mma_gemm<<<gd, 512, GEMM_SMEM>>>(Hhi, Hlo,
                                     WdThi, WdTlo, sdThi, sdTlo, ybuf,
                                     WdThi, WdTlo, sdThi, sdTlo, ybuf,
                                     list, 0, ws);
    // combine
    final_kernel<<<(NTOK * DIMD / 4) / 256, 256>>>(out);
}